// round 2
// baseline (speedup 1.0000x reference)
#include <cuda_runtime.h>
#include <cstdint>

// ---------------- problem constants (fixed shapes) ----------------
#define NB    883            // nodes per graph instance
#define BTI   96             // B*T instances
#define TOT   (NB*BTI)       // 84768 total node-instances
#define DIM   128            // feature dim (H*C)
#define FFD   2048           // feed-forward dim
#define EMAX  7168           // max base edges (actual 7000)

// ---------------- device scratch (static allocation only) ----------------
__device__ float g_xl [(size_t)TOT*DIM];
__device__ float g_xr [(size_t)TOT*DIM];
__device__ float g_agg[(size_t)TOT*DIM];     // gat output, later reused for FFN output
__device__ float g_h  [(size_t)TOT*DIM];
__device__ float g_ff1[(size_t)TOT*FFD];     // FFN hidden (~694 MB)

__device__ int g_src[EMAX];
__device__ int g_dst[EMAX];
__device__ int g_deg[NB];
__device__ int g_rowptr[NB+1];
__device__ int g_wp[NB];
__device__ int g_csr[EMAX+NB];
__device__ int g_flag;                       // 0 => edge_index is int64, else int32

// ---------------- CSR build ----------------
__global__ void k_init() {
    int t = threadIdx.x;
    if (t < NB) g_deg[t] = 1;                // self loop contributes 1 per node
    if (t == 0) g_flag = 0;
}

// If data is int64: words [2k+1] (high words of src row) are all zero.
// If data is int32: those words are random src values in [0,883) -> nonzero w.h.p.
__global__ void k_detect(const int* __restrict__ w, int E) {
    int k = blockIdx.x*blockDim.x + threadIdx.x;
    if (k < E) {
        if (w[2*k+1] != 0) atomicOr(&g_flag, 1);
    }
}

__global__ void k_decode(const int* __restrict__ w, int E) {
    int k = blockIdx.x*blockDim.x + threadIdx.x;
    if (k >= E) return;
    if (g_flag == 0) {   // int64 layout: element e -> words 2e (lo), 2e+1 (hi)
        g_src[k] = w[2*k];
        g_dst[k] = w[2*(E + k)];
    } else {             // int32 layout
        g_src[k] = w[k];
        g_dst[k] = w[E + k];
    }
}

__global__ void k_hist(int E) {
    int k = blockIdx.x*blockDim.x + threadIdx.x;
    if (k < E) atomicAdd(&g_deg[g_dst[k]], 1);
}

__global__ void k_scan() {   // single block, 1024 threads, NB=883 entries
    __shared__ int s[1024];
    int t = threadIdx.x;
    int v = (t < NB) ? g_deg[t] : 0;
    s[t] = v;
    __syncthreads();
    for (int off = 1; off < 1024; off <<= 1) {
        int u = (t >= off) ? s[t-off] : 0;
        __syncthreads();
        s[t] += u;
        __syncthreads();
    }
    if (t < NB) {
        g_rowptr[t+1] = s[t];
        g_wp[t]       = s[t] - v;   // exclusive prefix = write pointer
    }
    if (t == 0) g_rowptr[0] = 0;
}

__global__ void k_scatter(int E) {
    int j = blockIdx.x*blockDim.x + threadIdx.x;
    if (j >= E + NB) return;
    int s, d;
    if (j < E) { s = g_src[j]; d = g_dst[j]; }
    else       { s = d = j - E; }            // self loops
    int pos = atomicAdd(&g_wp[d], 1);
    g_csr[pos] = s;
}

// ---------------- fp32 SGEMM: C[M,N] = A[M,K] @ B[K,N] + bias (opt. ReLU) ----------------
// BM=BN=128, BK=16, 256 threads, 8x8 per thread. M guarded, N & K multiples of 128/16.
template<int RELU>
__global__ __launch_bounds__(256, 2) void sgemm(
    const float* __restrict__ A, const float* __restrict__ Bm,
    const float* __restrict__ bias, float* __restrict__ C,
    int M, int N, int K)
{
    __shared__ float As[16][128];   // k-major (transposed store)
    __shared__ float Bs[16][128];
    const int bm = blockIdx.x * 128;
    const int bn = blockIdx.y * 128;
    const int tid = threadIdx.x;
    const int tr = tid >> 4;            // 0..15
    const int tc = tid & 15;            // 0..15
    const int ar = tid >> 2;            // 0..63 (A row within tile, +64 for second)
    const int ak = (tid & 3) << 2;      // 0,4,8,12
    const int brr = tid >> 5;           // 0..7 (B k-row, +8 for second)
    const int bc = (tid & 31) << 2;     // 0..124

    float acc[8][8];
#pragma unroll
    for (int i = 0; i < 8; i++)
#pragma unroll
        for (int j = 0; j < 8; j++) acc[i][j] = 0.f;

    for (int k0 = 0; k0 < K; k0 += 16) {
        float4 a0 = make_float4(0.f,0.f,0.f,0.f), a1 = a0;
        if (bm + ar      < M) a0 = *(const float4*)(A + (size_t)(bm+ar   )*K + k0 + ak);
        if (bm + ar + 64 < M) a1 = *(const float4*)(A + (size_t)(bm+ar+64)*K + k0 + ak);
        float4 b0 = *(const float4*)(Bm + (size_t)(k0+brr  )*N + bn + bc);
        float4 b1 = *(const float4*)(Bm + (size_t)(k0+brr+8)*N + bn + bc);
        __syncthreads();
        As[ak+0][ar]    = a0.x; As[ak+1][ar]    = a0.y; As[ak+2][ar]    = a0.z; As[ak+3][ar]    = a0.w;
        As[ak+0][ar+64] = a1.x; As[ak+1][ar+64] = a1.y; As[ak+2][ar+64] = a1.z; As[ak+3][ar+64] = a1.w;
        *(float4*)&Bs[brr  ][bc] = b0;
        *(float4*)&Bs[brr+8][bc] = b1;
        __syncthreads();
#pragma unroll
        for (int kk = 0; kk < 16; kk++) {
            float ra[8], rb[8];
            *(float4*)(ra  )  = *(const float4*)&As[kk][(tr<<2)];
            *(float4*)(ra+4)  = *(const float4*)&As[kk][(tr<<2)+64];
            *(float4*)(rb  )  = *(const float4*)&Bs[kk][(tc<<2)];
            *(float4*)(rb+4)  = *(const float4*)&Bs[kk][(tc<<2)+64];
#pragma unroll
            for (int i = 0; i < 8; i++)
#pragma unroll
                for (int j = 0; j < 8; j++)
                    acc[i][j] = fmaf(ra[i], rb[j], acc[i][j]);
        }
    }

#pragma unroll
    for (int ih = 0; ih < 2; ih++)
#pragma unroll
        for (int i = 0; i < 4; i++) {
            int row = bm + ih*64 + (tr<<2) + i;
            if (row >= M) continue;
#pragma unroll
            for (int jh = 0; jh < 2; jh++) {
                int col = bn + jh*64 + (tc<<2);
                float4 v;
                v.x = acc[ih*4+i][jh*4+0] + bias[col+0];
                v.y = acc[ih*4+i][jh*4+1] + bias[col+1];
                v.z = acc[ih*4+i][jh*4+2] + bias[col+2];
                v.w = acc[ih*4+i][jh*4+3] + bias[col+3];
                if (RELU) {
                    v.x = fmaxf(v.x, 0.f); v.y = fmaxf(v.y, 0.f);
                    v.z = fmaxf(v.z, 0.f); v.w = fmaxf(v.w, 0.f);
                }
                *(float4*)(C + (size_t)row*N + col) = v;
            }
        }
}

// ---------------- GATv2 edge aggregation: online softmax per node-instance ----------------
// Block = one node-instance g. 128 threads: t = h*16 + c.
__global__ void k_edge(const float* __restrict__ att, const float* __restrict__ bias_gat)
{
    int g = blockIdx.x;
    int b = g / NB;
    int i = g - b*NB;
    int t = threadIdx.x;
    float attv = att[t];
    float rx = g_xr[(size_t)g*DIM + t];
    int e0 = g_rowptr[i], e1 = g_rowptr[i+1];
    int base = b * NB;
    float m = -1e30f, ss = 0.f, acc = 0.f;
    for (int e = e0; e < e1; e++) {
        int sg = base + g_csr[e];
        float v  = g_xl[(size_t)sg*DIM + t];
        float ev = v + rx;
        ev = ev > 0.f ? ev : 0.2f * ev;            // leaky_relu(0.2)
        float p = ev * attv;
#pragma unroll
        for (int o = 8; o >= 1; o >>= 1)
            p += __shfl_xor_sync(0xffffffffu, p, o, 16);   // sum over C within head
        float mn  = fmaxf(m, p);
        float f   = __expf(m - mn);
        float wgt = __expf(p - mn);
        ss  = ss  * f + wgt;
        acc = acc * f + wgt * v;
        m = mn;
    }
    g_agg[(size_t)g*DIM + t] = acc / ss + bias_gat[t];
}

// ---------------- LayerNorm(A + B) * gamma + beta ----------------
__global__ void k_ln(const float* __restrict__ A, const float* __restrict__ Badd,
                     const float* __restrict__ gamma, const float* __restrict__ beta,
                     float* __restrict__ out)
{
    int g = blockIdx.x, t = threadIdx.x;
    size_t idx = (size_t)g*DIM + t;
    float v = A[idx] + Badd[idx];
    __shared__ float red[4];
    int lane = t & 31, w = t >> 5;
    float s = v;
#pragma unroll
    for (int o = 16; o >= 1; o >>= 1) s += __shfl_xor_sync(0xffffffffu, s, o);
    if (lane == 0) red[w] = s;
    __syncthreads();
    float mu = (red[0]+red[1]+red[2]+red[3]) * (1.f/DIM);
    float d = v - mu;
    float q = d*d;
#pragma unroll
    for (int o = 16; o >= 1; o >>= 1) q += __shfl_xor_sync(0xffffffffu, q, o);
    __syncthreads();
    if (lane == 0) red[w] = q;
    __syncthreads();
    float var = (red[0]+red[1]+red[2]+red[3]) * (1.f/DIM);
    out[idx] = d * rsqrtf(var + 1e-5f) * gamma[t] + beta[t];
}

// ---------------- launcher ----------------
extern "C" void kernel_launch(void* const* d_in, const int* in_sizes, int n_in,
                              void* d_out, int out_size)
{
    const float* x   = (const float*)d_in[0];
    const int*   ei  = (const int*)  d_in[1];
    const float* Wl  = (const float*)d_in[2];
    const float* bl  = (const float*)d_in[3];
    const float* Wr  = (const float*)d_in[4];
    const float* brv = (const float*)d_in[5];
    const float* att = (const float*)d_in[6];
    const float* bg  = (const float*)d_in[7];
    const float* W1  = (const float*)d_in[8];
    const float* b1  = (const float*)d_in[9];
    const float* W2  = (const float*)d_in[10];
    const float* b2  = (const float*)d_in[11];
    const float* g1  = (const float*)d_in[12];
    const float* be1 = (const float*)d_in[13];
    const float* g2  = (const float*)d_in[14];
    const float* be2 = (const float*)d_in[15];
    float* out = (float*)d_out;

    int E = in_sizes[1] / 2;
    if (E > EMAX) E = EMAX;

    void *pxl, *pxr, *pagg, *ph, *pff1;
    cudaGetSymbolAddress(&pxl,  g_xl);
    cudaGetSymbolAddress(&pxr,  g_xr);
    cudaGetSymbolAddress(&pagg, g_agg);
    cudaGetSymbolAddress(&ph,   g_h);
    cudaGetSymbolAddress(&pff1, g_ff1);

    // CSR build (shared base graph across all 96 instances)
    int gE = (E + 255) / 256;
    k_init   <<<1, 1024>>>();
    k_detect <<<gE, 256>>>(ei, E);
    k_decode <<<gE, 256>>>(ei, E);
    k_hist   <<<gE, 256>>>(E);
    k_scan   <<<1, 1024>>>();
    k_scatter<<<(E + NB + 255) / 256, 256>>>(E);

    const int GM = (TOT + 127) / 128;   // 663

    // x_l = x@Wl + bl ; x_r = x@Wr + br
    sgemm<0><<<dim3(GM, 1),  256>>>(x, Wl, bl,  (float*)pxl,  TOT, DIM, DIM);
    sgemm<0><<<dim3(GM, 1),  256>>>(x, Wr, brv, (float*)pxr,  TOT, DIM, DIM);

    // GATv2 attention + aggregation (online softmax per node)
    k_edge<<<TOT, 128>>>(att, bg);

    // h = LN1(x + gat)
    k_ln<<<TOT, 128>>>(x, (float*)pagg, g1, be1, (float*)ph);

    // FFN: ff1 = relu(h@W1+b1); ff2 = ff1@W2+b2 (into g_agg)
    sgemm<1><<<dim3(GM, 16), 256>>>((const float*)ph,   W1, b1, (float*)pff1, TOT, FFD, DIM);
    sgemm<0><<<dim3(GM, 1),  256>>>((const float*)pff1, W2, b2, (float*)pagg, TOT, DIM, FFD);

    // out = LN2(h + ffn)
    k_ln<<<TOT, 128>>>((const float*)ph, (const float*)pagg, g2, be2, out);
}

// round 4
// speedup vs baseline: 1.5671x; 1.5671x over previous
#include <cuda_runtime.h>
#include <cuda_bf16.h>
#include <cstdint>

// ---------------- problem constants ----------------
#define NB    883
#define BTI   96
#define TOT   (NB*BTI)       // 84768
#define DIM   128
#define FFD   2048
#define EMAX  7168

// ---------------- device scratch ----------------
__device__ float g_xl [(size_t)TOT*DIM];
__device__ float g_xr [(size_t)TOT*DIM];     // reused as bf16 h_hi/h_lo after k_edge
__device__ float g_agg[(size_t)TOT*DIM];
__device__ float g_h  [(size_t)TOT*DIM];
__device__ float g_ff1[(size_t)TOT*FFD];     // reused as bf16 ff1_hi/ff1_lo
__device__ __nv_bfloat16 g_xb [(size_t)2*TOT*DIM];
__device__ __nv_bfloat16 g_wlt[2*DIM*DIM];
__device__ __nv_bfloat16 g_wrt[2*DIM*DIM];
__device__ __nv_bfloat16 g_w1t[2*DIM*FFD];
__device__ __nv_bfloat16 g_w2t[2*DIM*FFD];

__device__ int g_src[EMAX];
__device__ int g_dst[EMAX];
__device__ int g_deg[NB];
__device__ int g_rowptr[NB+1];
__device__ int g_wp[NB];
__device__ int g_csr[EMAX+NB];
__device__ int g_flag;

// ---------------- helpers ----------------
__device__ __forceinline__ uint32_t smem_u32(const void* p) {
    uint32_t a;
    asm("{ .reg .u64 t; cvta.to.shared.u64 t, %1; cvt.u32.u64 %0, t; }" : "=r"(a) : "l"(p));
    return a;
}
__device__ __forceinline__ void cp16(uint32_t s, const void* g) {
    asm volatile("cp.async.cg.shared.global [%0], [%1], 16;" :: "r"(s), "l"(g));
}
#define CP_COMMIT() asm volatile("cp.async.commit_group;" ::: "memory")
#define CP_WAIT1()  asm volatile("cp.async.wait_group 1;" ::: "memory")

__device__ __forceinline__ void ldm4(uint32_t* r, uint32_t addr) {
    asm volatile("ldmatrix.sync.aligned.m8n8.x4.shared.b16 {%0,%1,%2,%3}, [%4];"
        : "=r"(r[0]), "=r"(r[1]), "=r"(r[2]), "=r"(r[3]) : "r"(addr));
}
__device__ __forceinline__ void mma16816(float* d, const uint32_t* a, const uint32_t* b) {
    asm volatile(
        "mma.sync.aligned.m16n8k16.row.col.f32.bf16.bf16.f32 "
        "{%0,%1,%2,%3}, {%4,%5,%6,%7}, {%8,%9}, {%0,%1,%2,%3};"
        : "+f"(d[0]), "+f"(d[1]), "+f"(d[2]), "+f"(d[3])
        : "r"(a[0]), "r"(a[1]), "r"(a[2]), "r"(a[3]), "r"(b[0]), "r"(b[1]));
}

// ==================================================================================
// bf16x3 GEMM via mma.sync: C[M,N] = A[M,K] @ B[N,K]^T  (A,B given as hi/lo splits)
// BM=128, BN=128, BK=32, 3-stage cp.async, 256 threads, warp = 32x64.
// smem per stage: Ahi,Alo,Bhi,Blo each 128 rows x 80B (64B data + 16B pad) = 40960B
// ==================================================================================
#define SROWB   80
#define ARRB    (128*SROWB)          // 10240
#define STAGEB  (4*ARRB)             // 40960
#define GSMEM   (3*STAGEB)           // 122880

__global__ void __launch_bounds__(256) mmagemm(
    const __nv_bfloat16* __restrict__ Ahi, const __nv_bfloat16* __restrict__ Alo,
    const __nv_bfloat16* __restrict__ Bhi, const __nv_bfloat16* __restrict__ Blo,
    const float* __restrict__ bias, float* __restrict__ C,
    __nv_bfloat16* __restrict__ Ohi, __nv_bfloat16* __restrict__ Olo,
    int M, int N, int K, int relu)
{
    extern __shared__ char smem[];
    const uint32_t sb = smem_u32(smem);
    const int tid = threadIdx.x;
    const int lane = tid & 31, wid = tid >> 5;
    const int wm = wid & 3, wn = wid >> 2;
    const int bm = blockIdx.x * 128, bn = blockIdx.y * 128;
    const int nk = K >> 5;

    // per-thread load pattern: 8 chunks of 16B
    int cid[8], crow[8], ccol[8];
#pragma unroll
    for (int j = 0; j < 8; j++) {
        int id = tid + 256 * j;
        cid[j] = id >> 9;                 // 0=Ahi 1=Alo 2=Bhi 3=Blo
        int c = id & 511;
        crow[j] = c >> 2;
        ccol[j] = c & 3;
    }
    const __nv_bfloat16* srcp[4] = { Ahi, Alo, Bhi, Blo };

    auto load_stage = [&](int st, int kc) {
        int k0 = kc << 5;
        uint32_t base = sb + st * STAGEB;
#pragma unroll
        for (int j = 0; j < 8; j++) {
            int arr = cid[j], row = crow[j], col = ccol[j];
            int gr = (arr < 2) ? min(bm + row, M - 1) : (bn + row);
            const __nv_bfloat16* g = srcp[arr] + (size_t)gr * K + k0 + col * 8;
            cp16(base + arr * ARRB + row * SROWB + col * 16, g);
        }
        CP_COMMIT();
    };

    float acc[2][8][4];
#pragma unroll
    for (int mi = 0; mi < 2; mi++)
#pragma unroll
        for (int ni = 0; ni < 8; ni++)
#pragma unroll
            for (int q = 0; q < 4; q++) acc[mi][ni][q] = 0.f;

    // ldmatrix lane addresses (byte offsets within an array)
    const uint32_t aoff = (uint32_t)((wm * 32 + (lane & 15)) * SROWB + ((lane >> 4) * 16));
    const uint32_t boff = (uint32_t)((wn * 64 + (lane & 7) + ((lane >> 4) << 3)) * SROWB
                                     + (((lane >> 3) & 1) * 16));

    load_stage(0, 0);
    load_stage(1, 1);

    for (int c = 0; c < nk; c++) {
        CP_WAIT1();
        __syncthreads();
        if (c + 2 < nk) load_stage((c + 2) % 3, c + 2);
        else CP_COMMIT();

        uint32_t s = sb + (c % 3) * STAGEB;
        uint32_t sAh = s, sAl = s + ARRB, sBh = s + 2 * ARRB, sBl = s + 3 * ARRB;
#pragma unroll
        for (int kk = 0; kk < 2; kk++) {
            uint32_t kb = kk * 32;
            uint32_t ah[2][4], al[2][4], bh[4][4], bl[4][4];
#pragma unroll
            for (int mi = 0; mi < 2; mi++) {
                ldm4(ah[mi], sAh + aoff + mi * (16 * SROWB) + kb);
                ldm4(al[mi], sAl + aoff + mi * (16 * SROWB) + kb);
            }
#pragma unroll
            for (int p = 0; p < 4; p++) {
                ldm4(bh[p], sBh + boff + p * (16 * SROWB) + kb);
                ldm4(bl[p], sBl + boff + p * (16 * SROWB) + kb);
            }
#pragma unroll
            for (int mi = 0; mi < 2; mi++)
#pragma unroll
                for (int ni = 0; ni < 8; ni++) {
                    const uint32_t* ph = &bh[ni >> 1][(ni & 1) * 2];
                    const uint32_t* pl = &bl[ni >> 1][(ni & 1) * 2];
                    mma16816(acc[mi][ni], ah[mi], ph);
                    mma16816(acc[mi][ni], ah[mi], pl);
                    mma16816(acc[mi][ni], al[mi], ph);
                }
        }
        __syncthreads();
    }

    // epilogue
#pragma unroll
    for (int mi = 0; mi < 2; mi++) {
#pragma unroll
        for (int ni = 0; ni < 8; ni++) {
            int row0 = bm + wm * 32 + mi * 16 + (lane >> 2);
            int col  = bn + wn * 64 + ni * 8 + (lane & 3) * 2;
            float b0 = __ldg(bias + col), b1 = __ldg(bias + col + 1);
#pragma unroll
            for (int half = 0; half < 2; half++) {
                int row = row0 + half * 8;
                if (row >= M) continue;
                float v0 = acc[mi][ni][half * 2 + 0] + b0;
                float v1 = acc[mi][ni][half * 2 + 1] + b1;
                if (relu) { v0 = fmaxf(v0, 0.f); v1 = fmaxf(v1, 0.f); }
                if (C) {
                    float2 q = make_float2(v0, v1);
                    *(float2*)(C + (size_t)row * N + col) = q;
                }
                if (Ohi) {
                    __nv_bfloat16 h0 = __float2bfloat16(v0);
                    __nv_bfloat16 h1 = __float2bfloat16(v1);
                    __nv_bfloat162 hh; hh.x = h0; hh.y = h1;
                    *(__nv_bfloat162*)(Ohi + (size_t)row * N + col) = hh;
                    __nv_bfloat162 ll;
                    ll.x = __float2bfloat16(v0 - __bfloat162float(h0));
                    ll.y = __float2bfloat16(v1 - __bfloat162float(h1));
                    *(__nv_bfloat162*)(Olo + (size_t)row * N + col) = ll;
                }
            }
        }
    }
}

// ---------------- conversion kernels ----------------
__global__ void k_cvt_x(const float* __restrict__ x, __nv_bfloat16* __restrict__ hi,
                        __nv_bfloat16* __restrict__ lo, long n4)
{
    long i = blockIdx.x * (long)blockDim.x + threadIdx.x;
    if (i >= n4) return;
    float4 v = ((const float4*)x)[i];
    long s = i * 4;
    __nv_bfloat16 h0 = __float2bfloat16(v.x), h1 = __float2bfloat16(v.y);
    __nv_bfloat16 h2 = __float2bfloat16(v.z), h3 = __float2bfloat16(v.w);
    __nv_bfloat162 a; a.x = h0; a.y = h1; *(__nv_bfloat162*)(hi + s)     = a;
    __nv_bfloat162 b; b.x = h2; b.y = h3; *(__nv_bfloat162*)(hi + s + 2) = b;
    __nv_bfloat162 c; c.x = __float2bfloat16(v.x - __bfloat162float(h0));
                      c.y = __float2bfloat16(v.y - __bfloat162float(h1));
    *(__nv_bfloat162*)(lo + s) = c;
    __nv_bfloat162 d; d.x = __float2bfloat16(v.z - __bfloat162float(h2));
                      d.y = __float2bfloat16(v.w - __bfloat162float(h3));
    *(__nv_bfloat162*)(lo + s + 2) = d;
}

__global__ void k_cvt_w(const float* __restrict__ W, __nv_bfloat16* __restrict__ hi,
                        __nv_bfloat16* __restrict__ lo, int K, int N)
{
    int i = blockIdx.x * blockDim.x + threadIdx.x;
    if (i >= K * N) return;
    int k = i / N, n = i - k * N;
    float v = W[i];
    __nv_bfloat16 h = __float2bfloat16(v);
    hi[(size_t)n * K + k] = h;
    lo[(size_t)n * K + k] = __float2bfloat16(v - __bfloat162float(h));
}

// ---------------- CSR build ----------------
__global__ void k_init() {
    int t = threadIdx.x;
    if (t < NB) g_deg[t] = 1;
    if (t == 0) g_flag = 0;
}
__global__ void k_detect(const int* __restrict__ w, int E) {
    int k = blockIdx.x * blockDim.x + threadIdx.x;
    if (k < E && w[2 * k + 1] != 0) atomicOr(&g_flag, 1);
}
__global__ void k_decode(const int* __restrict__ w, int E) {
    int k = blockIdx.x * blockDim.x + threadIdx.x;
    if (k >= E) return;
    if (g_flag == 0) { g_src[k] = w[2 * k]; g_dst[k] = w[2 * (E + k)]; }
    else             { g_src[k] = w[k];     g_dst[k] = w[E + k]; }
}
__global__ void k_hist(int E) {
    int k = blockIdx.x * blockDim.x + threadIdx.x;
    if (k < E) atomicAdd(&g_deg[g_dst[k]], 1);
}
__global__ void k_scan() {
    __shared__ int s[1024];
    int t = threadIdx.x;
    int v = (t < NB) ? g_deg[t] : 0;
    s[t] = v;
    __syncthreads();
    for (int off = 1; off < 1024; off <<= 1) {
        int u = (t >= off) ? s[t - off] : 0;
        __syncthreads();
        s[t] += u;
        __syncthreads();
    }
    if (t < NB) { g_rowptr[t + 1] = s[t]; g_wp[t] = s[t] - v; }
    if (t == 0) g_rowptr[0] = 0;
}
__global__ void k_scatter(int E) {
    int j = blockIdx.x * blockDim.x + threadIdx.x;
    if (j >= E + NB) return;
    int s, d;
    if (j < E) { s = g_src[j]; d = g_dst[j]; }
    else       { s = d = j - E; }
    g_csr[atomicAdd(&g_wp[d], 1)] = s;
}

// ---------------- GATv2 edge aggregation (online softmax) ----------------
__global__ void k_edge(const float* __restrict__ att, const float* __restrict__ bias_gat)
{
    int g = blockIdx.x;
    int b = g / NB;
    int i = g - b * NB;
    int t = threadIdx.x;
    float attv = att[t];
    float rx = g_xr[(size_t)g * DIM + t];
    int e0 = g_rowptr[i], e1 = g_rowptr[i + 1];
    int base = b * NB;
    float m = -1e30f, ss = 0.f, acc = 0.f;
    for (int e = e0; e < e1; e++) {
        int sg = base + g_csr[e];
        float v  = g_xl[(size_t)sg * DIM + t];
        float ev = v + rx;
        ev = ev > 0.f ? ev : 0.2f * ev;
        float p = ev * attv;
#pragma unroll
        for (int o = 8; o >= 1; o >>= 1)
            p += __shfl_xor_sync(0xffffffffu, p, o, 16);
        float mn = fmaxf(m, p);
        float f  = __expf(m - mn);
        float w  = __expf(p - mn);
        ss  = ss  * f + w;
        acc = acc * f + w * v;
        m = mn;
    }
    g_agg[(size_t)g * DIM + t] = acc / ss + bias_gat[t];
}

// ---------------- LayerNorms ----------------
__global__ void k_ln1(const float* __restrict__ A, const float* __restrict__ Badd,
                      const float* __restrict__ gamma, const float* __restrict__ beta,
                      float* __restrict__ out,
                      __nv_bfloat16* __restrict__ ohi, __nv_bfloat16* __restrict__ olo)
{
    int g = blockIdx.x, t = threadIdx.x;
    size_t idx = (size_t)g * DIM + t;
    float v = A[idx] + Badd[idx];
    __shared__ float red[4];
    int lane = t & 31, w = t >> 5;
    float s = v;
#pragma unroll
    for (int o = 16; o >= 1; o >>= 1) s += __shfl_xor_sync(0xffffffffu, s, o);
    if (lane == 0) red[w] = s;
    __syncthreads();
    float mu = (red[0] + red[1] + red[2] + red[3]) * (1.f / DIM);
    float d = v - mu;
    float q = d * d;
#pragma unroll
    for (int o = 16; o >= 1; o >>= 1) q += __shfl_xor_sync(0xffffffffu, q, o);
    __syncthreads();
    if (lane == 0) red[w] = q;
    __syncthreads();
    float var = (red[0] + red[1] + red[2] + red[3]) * (1.f / DIM);
    float r = d * rsqrtf(var + 1e-5f) * gamma[t] + beta[t];
    out[idx] = r;
    __nv_bfloat16 h = __float2bfloat16(r);
    ohi[idx] = h;
    olo[idx] = __float2bfloat16(r - __bfloat162float(h));
}

__global__ void k_ln(const float* __restrict__ A, const float* __restrict__ Badd,
                     const float* __restrict__ gamma, const float* __restrict__ beta,
                     float* __restrict__ out)
{
    int g = blockIdx.x, t = threadIdx.x;
    size_t idx = (size_t)g * DIM + t;
    float v = A[idx] + Badd[idx];
    __shared__ float red[4];
    int lane = t & 31, w = t >> 5;
    float s = v;
#pragma unroll
    for (int o = 16; o >= 1; o >>= 1) s += __shfl_xor_sync(0xffffffffu, s, o);
    if (lane == 0) red[w] = s;
    __syncthreads();
    float mu = (red[0] + red[1] + red[2] + red[3]) * (1.f / DIM);
    float d = v - mu;
    float q = d * d;
#pragma unroll
    for (int o = 16; o >= 1; o >>= 1) q += __shfl_xor_sync(0xffffffffu, q, o);
    __syncthreads();
    if (lane == 0) red[w] = q;
    __syncthreads();
    float var = (red[0] + red[1] + red[2] + red[3]) * (1.f / DIM);
    out[idx] = d * rsqrtf(var + 1e-5f) * gamma[t] + beta[t];
}

// ---------------- launcher ----------------
extern "C" void kernel_launch(void* const* d_in, const int* in_sizes, int n_in,
                              void* d_out, int out_size)
{
    const float* x   = (const float*)d_in[0];
    const int*   ei  = (const int*)  d_in[1];
    const float* Wl  = (const float*)d_in[2];
    const float* bl  = (const float*)d_in[3];
    const float* Wr  = (const float*)d_in[4];
    const float* brv = (const float*)d_in[5];
    const float* att = (const float*)d_in[6];
    const float* bg  = (const float*)d_in[7];
    const float* W1  = (const float*)d_in[8];
    const float* b1  = (const float*)d_in[9];
    const float* W2  = (const float*)d_in[10];
    const float* b2  = (const float*)d_in[11];
    const float* g1  = (const float*)d_in[12];
    const float* be1 = (const float*)d_in[13];
    const float* g2  = (const float*)d_in[14];
    const float* be2 = (const float*)d_in[15];
    float* out = (float*)d_out;

    int E = in_sizes[1] / 2;
    if (E > EMAX) E = EMAX;

    cudaFuncSetAttribute(mmagemm, cudaFuncAttributeMaxDynamicSharedMemorySize, GSMEM);

    void *pxl, *pxr, *pagg, *ph, *pff1, *pxb, *pwlt, *pwrt, *pw1t, *pw2t;
    cudaGetSymbolAddress(&pxl,  g_xl);
    cudaGetSymbolAddress(&pxr,  g_xr);
    cudaGetSymbolAddress(&pagg, g_agg);
    cudaGetSymbolAddress(&ph,   g_h);
    cudaGetSymbolAddress(&pff1, g_ff1);
    cudaGetSymbolAddress(&pxb,  g_xb);
    cudaGetSymbolAddress(&pwlt, g_wlt);
    cudaGetSymbolAddress(&pwrt, g_wrt);
    cudaGetSymbolAddress(&pw1t, g_w1t);
    cudaGetSymbolAddress(&pw2t, g_w2t);

    __nv_bfloat16* xbh = (__nv_bfloat16*)pxb;
    __nv_bfloat16* xbl = xbh + (size_t)TOT * DIM;
    __nv_bfloat16* wlh = (__nv_bfloat16*)pwlt; __nv_bfloat16* wll = wlh + DIM * DIM;
    __nv_bfloat16* wrh = (__nv_bfloat16*)pwrt; __nv_bfloat16* wrl = wrh + DIM * DIM;
    __nv_bfloat16* w1h = (__nv_bfloat16*)pw1t; __nv_bfloat16* w1l = w1h + DIM * FFD;
    __nv_bfloat16* w2h = (__nv_bfloat16*)pw2t; __nv_bfloat16* w2l = w2h + DIM * FFD;
    __nv_bfloat16* hh  = (__nv_bfloat16*)pxr;  __nv_bfloat16* hl  = hh + (size_t)TOT * DIM;
    __nv_bfloat16* fh  = (__nv_bfloat16*)pff1; __nv_bfloat16* fl  = fh + (size_t)TOT * FFD;

    // CSR build (base graph shared across instances)
    int gE = (E + 255) / 256;
    k_init   <<<1, 1024>>>();
    k_detect <<<gE, 256>>>(ei, E);
    k_decode <<<gE, 256>>>(ei, E);
    k_hist   <<<gE, 256>>>(E);
    k_scan   <<<1, 1024>>>();
    k_scatter<<<(E + NB + 255) / 256, 256>>>(E);

    // hi/lo conversions
    long n4 = (long)TOT * DIM / 4;
    k_cvt_x<<<(int)((n4 + 255) / 256), 256>>>(x, xbh, xbl, n4);
    k_cvt_w<<<(DIM * DIM + 255) / 256, 256>>>(Wl, wlh, wll, DIM, DIM);
    k_cvt_w<<<(DIM * DIM + 255) / 256, 256>>>(Wr, wrh, wrl, DIM, DIM);
    k_cvt_w<<<(DIM * FFD + 255) / 256, 256>>>(W1, w1h, w1l, DIM, FFD);
    k_cvt_w<<<(DIM * FFD + 255) / 256, 256>>>(W2, w2h, w2l, FFD, DIM);

    const int GM = (TOT + 127) / 128;   // 663

    // x_l = x@Wl + bl ; x_r = x@Wr + br
    mmagemm<<<dim3(GM, 1), 256, GSMEM>>>(xbh, xbl, wlh, wll, bl,
        (float*)pxl, nullptr, nullptr, TOT, DIM, DIM, 0);
    mmagemm<<<dim3(GM, 1), 256, GSMEM>>>(xbh, xbl, wrh, wrl, brv,
        (float*)pxr, nullptr, nullptr, TOT, DIM, DIM, 0);

    // GATv2 aggregation
    k_edge<<<TOT, 128>>>(att, bg);

    // h = LN1(x + gat) ; also emit bf16 hi/lo (reusing g_xr)
    k_ln1<<<TOT, 128>>>(x, (const float*)pagg, g1, be1, (float*)ph, hh, hl);

    // ff1 = relu(h@W1 + b1) -> bf16 hi/lo only
    mmagemm<<<dim3(GM, 16), 256, GSMEM>>>(hh, hl, w1h, w1l, b1,
        nullptr, fh, fl, TOT, FFD, DIM, 1);

    // ffn = ff1@W2 + b2 -> fp32 (g_agg)
    mmagemm<<<dim3(GM, 1), 256, GSMEM>>>(fh, fl, w2h, w2l, b2,
        (float*)pagg, nullptr, nullptr, TOT, DIM, FFD, 0);

    // out = LN2(h + ffn)
    k_ln<<<TOT, 128>>>((const float*)ph, (const float*)pagg, g2, be2, out);
}

// round 5
// speedup vs baseline: 2.2722x; 1.4500x over previous
#include <cuda_runtime.h>
#include <cuda_fp16.h>
#include <cstdint>

// ---------------- problem constants ----------------
#define NB    883
#define BTI   96
#define TOT   (NB*BTI)       // 84768
#define DIM   128
#define FFD   2048
#define EMAX  7168

// ---------------- device scratch ----------------
__device__ float g_agg[(size_t)TOT*DIM];
__device__ float g_h  [(size_t)TOT*DIM];
__device__ float g_hb [(size_t)TOT*DIM];     // h hi/lo (half): 2*TOT*DIM halves
__device__ float g_ff1[(size_t)TOT*FFD];     // xlr fp32 (TOT*256) early; ff1 hi/lo half later
__device__ __half g_xb [(size_t)2*TOT*DIM];  // x hi/lo
__device__ __half g_wlrt[256*DIM];           // [Wl;Wr] transposed: [256, 128]
__device__ __half g_w1t[(size_t)FFD*DIM];    // W1^T [2048,128]
__device__ __half g_w2t[(size_t)DIM*FFD];    // W2^T [128,2048]
__device__ float  g_blr[256];

__device__ int g_src[EMAX];
__device__ int g_dst[EMAX];
__device__ int g_deg[NB];
__device__ int g_rowptr[NB+1];
__device__ int g_wp[NB];
__device__ int g_csr[EMAX+NB];
__device__ int g_flag;

// ---------------- helpers ----------------
__device__ __forceinline__ uint32_t smem_u32(const void* p) {
    uint32_t a;
    asm("{ .reg .u64 t; cvta.to.shared.u64 t, %1; cvt.u32.u64 %0, t; }" : "=r"(a) : "l"(p));
    return a;
}
__device__ __forceinline__ void cp16(uint32_t s, const void* g) {
    asm volatile("cp.async.cg.shared.global [%0], [%1], 16;" :: "r"(s), "l"(g));
}
#define CP_COMMIT() asm volatile("cp.async.commit_group;" ::: "memory")
#define CP_WAIT1()  asm volatile("cp.async.wait_group 1;" ::: "memory")

__device__ __forceinline__ void ldm4(uint32_t* r, uint32_t addr) {
    asm volatile("ldmatrix.sync.aligned.m8n8.x4.shared.b16 {%0,%1,%2,%3}, [%4];"
        : "=r"(r[0]), "=r"(r[1]), "=r"(r[2]), "=r"(r[3]) : "r"(addr));
}
__device__ __forceinline__ void mma16816(float* d, const uint32_t* a, const uint32_t* b) {
    asm volatile(
        "mma.sync.aligned.m16n8k16.row.col.f32.f16.f16.f32 "
        "{%0,%1,%2,%3}, {%4,%5,%6,%7}, {%8,%9}, {%0,%1,%2,%3};"
        : "+f"(d[0]), "+f"(d[1]), "+f"(d[2]), "+f"(d[3])
        : "r"(a[0]), "r"(a[1]), "r"(a[2]), "r"(a[3]), "r"(b[0]), "r"(b[1]));
}

// ==================================================================================
// fp16x2 GEMM via mma.sync: C[M,N] = (Ahi+Alo)[M,K] @ B[N,K]^T
// BM=128, BN=128, BK=32, 3-stage cp.async, 256 threads, warp tile 32x64, 2 CTA/SM.
// smem per stage: Ahi, Alo, B each 128 rows x 80B (64B data + 16B pad)
// ==================================================================================
#define SROWB   80
#define ARRB    (128*SROWB)          // 10240
#define STAGEB  (3*ARRB)             // 30720
#define GSMEM   (3*STAGEB)           // 92160

__global__ void __launch_bounds__(256, 2) mmagemm(
    const __half* __restrict__ Ahi, const __half* __restrict__ Alo,
    const __half* __restrict__ B,
    const float* __restrict__ bias, float* __restrict__ C,
    __half* __restrict__ Ohi, __half* __restrict__ Olo,
    int M, int N, int K, int relu)
{
    extern __shared__ char smem[];
    const uint32_t sb = smem_u32(smem);
    const int tid = threadIdx.x;
    const int lane = tid & 31, wid = tid >> 5;
    const int wm = wid & 3, wn = wid >> 2;
    const int bm = blockIdx.x * 128, bn = blockIdx.y * 128;
    const int nk = K >> 5;

    auto load_stage = [&](int st, int kc) {
        int k0 = kc << 5;
        uint32_t base = sb + st * STAGEB;
#pragma unroll
        for (int j = 0; j < 6; j++) {
            int id = tid + 256 * j;
            int arr = id >> 9;            // 0=Ahi 1=Alo 2=B
            int c = id & 511;
            int row = c >> 2, col = c & 3;
            const __half* src = (arr == 0) ? Ahi : (arr == 1) ? Alo : B;
            int gr = (arr < 2) ? min(bm + row, M - 1) : (bn + row);
            cp16(base + arr * ARRB + row * SROWB + col * 16,
                 src + (size_t)gr * K + k0 + col * 8);
        }
        CP_COMMIT();
    };

    float acc[2][8][4];
#pragma unroll
    for (int mi = 0; mi < 2; mi++)
#pragma unroll
        for (int ni = 0; ni < 8; ni++)
#pragma unroll
            for (int q = 0; q < 4; q++) acc[mi][ni][q] = 0.f;

    const uint32_t aoff = (uint32_t)((wm * 32 + (lane & 15)) * SROWB + ((lane >> 4) * 16));
    const uint32_t boff = (uint32_t)((wn * 64 + (lane & 7) + ((lane >> 4) << 3)) * SROWB
                                     + (((lane >> 3) & 1) * 16));

    load_stage(0, 0);
    load_stage(1, 1);

    for (int c = 0; c < nk; c++) {
        CP_WAIT1();
        __syncthreads();
        if (c + 2 < nk) load_stage((c + 2) % 3, c + 2);
        else CP_COMMIT();

        uint32_t s = sb + (c % 3) * STAGEB;
        uint32_t sAh = s, sAl = s + ARRB, sB = s + 2 * ARRB;
#pragma unroll
        for (int kk = 0; kk < 2; kk++) {
            uint32_t kb = kk * 32;
            uint32_t ah[2][4], al[2][4], bf[4][4];
#pragma unroll
            for (int mi = 0; mi < 2; mi++) {
                ldm4(ah[mi], sAh + aoff + mi * (16 * SROWB) + kb);
                ldm4(al[mi], sAl + aoff + mi * (16 * SROWB) + kb);
            }
#pragma unroll
            for (int p = 0; p < 4; p++)
                ldm4(bf[p], sB + boff + p * (16 * SROWB) + kb);
#pragma unroll
            for (int mi = 0; mi < 2; mi++)
#pragma unroll
                for (int ni = 0; ni < 8; ni++) {
                    const uint32_t* pb = &bf[ni >> 1][(ni & 1) * 2];
                    mma16816(acc[mi][ni], ah[mi], pb);
                    mma16816(acc[mi][ni], al[mi], pb);
                }
        }
        __syncthreads();
    }

    // epilogue
#pragma unroll
    for (int mi = 0; mi < 2; mi++) {
#pragma unroll
        for (int ni = 0; ni < 8; ni++) {
            int row0 = bm + wm * 32 + mi * 16 + (lane >> 2);
            int col  = bn + wn * 64 + ni * 8 + (lane & 3) * 2;
            float b0 = __ldg(bias + col), b1 = __ldg(bias + col + 1);
#pragma unroll
            for (int half_ = 0; half_ < 2; half_++) {
                int row = row0 + half_ * 8;
                if (row >= M) continue;
                float v0 = acc[mi][ni][half_ * 2 + 0] + b0;
                float v1 = acc[mi][ni][half_ * 2 + 1] + b1;
                if (relu) { v0 = fmaxf(v0, 0.f); v1 = fmaxf(v1, 0.f); }
                if (C) {
                    *(float2*)(C + (size_t)row * N + col) = make_float2(v0, v1);
                }
                if (Ohi) {
                    __half h0 = __float2half(v0);
                    __half h1 = __float2half(v1);
                    __half2 hh; hh.x = h0; hh.y = h1;
                    *(__half2*)(Ohi + (size_t)row * N + col) = hh;
                    __half2 ll;
                    ll.x = __float2half(v0 - __half2float(h0));
                    ll.y = __float2half(v1 - __half2float(h1));
                    *(__half2*)(Olo + (size_t)row * N + col) = ll;
                }
            }
        }
    }
}

// ---------------- conversion kernels ----------------
__global__ void k_cvt_x(const float* __restrict__ x, __half* __restrict__ hi,
                        __half* __restrict__ lo, long n4)
{
    long i = blockIdx.x * (long)blockDim.x + threadIdx.x;
    if (i >= n4) return;
    float4 v = ((const float4*)x)[i];
    long s = i * 4;
    __half h0 = __float2half(v.x), h1 = __float2half(v.y);
    __half h2 = __float2half(v.z), h3 = __float2half(v.w);
    __half2 a; a.x = h0; a.y = h1; *(__half2*)(hi + s)     = a;
    __half2 b; b.x = h2; b.y = h3; *(__half2*)(hi + s + 2) = b;
    __half2 c; c.x = __float2half(v.x - __half2float(h0));
               c.y = __float2half(v.y - __half2float(h1));
    *(__half2*)(lo + s) = c;
    __half2 d; d.x = __float2half(v.z - __half2float(h2));
               d.y = __float2half(v.w - __half2float(h3));
    *(__half2*)(lo + s + 2) = d;
}

// transpose: W[K,N] -> out[N,K] fp16
__global__ void k_cvt_w(const float* __restrict__ W, __half* __restrict__ out, int K, int N)
{
    int i = blockIdx.x * blockDim.x + threadIdx.x;
    if (i >= K * N) return;
    int k = i / N, n = i - k * N;
    out[(size_t)n * K + k] = __float2half(W[i]);
}

__global__ void k_pack_bias(const float* __restrict__ bl, const float* __restrict__ br)
{
    int t = threadIdx.x;
    if (t < 128) g_blr[t] = bl[t];
    else         g_blr[t] = br[t - 128];
}

// ---------------- CSR build ----------------
__global__ void k_init() {
    int t = threadIdx.x;
    if (t < NB) g_deg[t] = 1;
    if (t == 0) g_flag = 0;
}
__global__ void k_detect(const int* __restrict__ w, int E) {
    int k = blockIdx.x * blockDim.x + threadIdx.x;
    if (k < E && w[2 * k + 1] != 0) atomicOr(&g_flag, 1);
}
__global__ void k_decode(const int* __restrict__ w, int E) {
    int k = blockIdx.x * blockDim.x + threadIdx.x;
    if (k >= E) return;
    if (g_flag == 0) { g_src[k] = w[2 * k]; g_dst[k] = w[2 * (E + k)]; }
    else             { g_src[k] = w[k];     g_dst[k] = w[E + k]; }
}
__global__ void k_hist(int E) {
    int k = blockIdx.x * blockDim.x + threadIdx.x;
    if (k < E) atomicAdd(&g_deg[g_dst[k]], 1);
}
__global__ void k_scan() {
    __shared__ int s[1024];
    int t = threadIdx.x;
    int v = (t < NB) ? g_deg[t] : 0;
    s[t] = v;
    __syncthreads();
    for (int off = 1; off < 1024; off <<= 1) {
        int u = (t >= off) ? s[t - off] : 0;
        __syncthreads();
        s[t] += u;
        __syncthreads();
    }
    if (t < NB) { g_rowptr[t + 1] = s[t]; g_wp[t] = s[t] - v; }
    if (t == 0) g_rowptr[0] = 0;
}
__global__ void k_scatter(int E) {
    int j = blockIdx.x * blockDim.x + threadIdx.x;
    if (j >= E + NB) return;
    int s, d;
    if (j < E) { s = g_src[j]; d = g_dst[j]; }
    else       { s = d = j - E; }
    g_csr[atomicAdd(&g_wp[d], 1)] = s;
}

// ---------------- GATv2 edge aggregation ----------------
// xlr: [TOT, 256] fp32, cols 0-127 = x_l, 128-255 = x_r.
// Scores are O(1) in magnitude -> plain exp softmax (no max-subtraction needed),
// which removes the serial dependency chain through the running max.
__global__ void k_edge(const float* __restrict__ xlr,
                       const float* __restrict__ att, const float* __restrict__ bias_gat)
{
    int g = blockIdx.x;
    int b = g / NB;
    int i = g - b * NB;
    int t = threadIdx.x;
    float attv = att[t];
    float rx = xlr[(size_t)g * 256 + 128 + t];
    int e0 = g_rowptr[i], e1 = g_rowptr[i + 1];
    int base = b * NB;
    float ss = 0.f, acc = 0.f;
#pragma unroll 2
    for (int e = e0; e < e1; e++) {
        int sg = base + g_csr[e];
        float v  = xlr[(size_t)sg * 256 + t];
        float ev = v + rx;
        ev = ev > 0.f ? ev : 0.2f * ev;
        float p = ev * attv;
#pragma unroll
        for (int o = 8; o >= 1; o >>= 1)
            p += __shfl_xor_sync(0xffffffffu, p, o, 16);
        float w = __expf(p);
        ss  += w;
        acc += w * v;
    }
    g_agg[(size_t)g * DIM + t] = acc / ss + bias_gat[t];
}

// ---------------- LayerNorms ----------------
__global__ void k_ln1(const float* __restrict__ A, const float* __restrict__ Badd,
                      const float* __restrict__ gamma, const float* __restrict__ beta,
                      float* __restrict__ out,
                      __half* __restrict__ ohi, __half* __restrict__ olo)
{
    int g = blockIdx.x, t = threadIdx.x;
    size_t idx = (size_t)g * DIM + t;
    float v = A[idx] + Badd[idx];
    __shared__ float red[4];
    int lane = t & 31, w = t >> 5;
    float s = v;
#pragma unroll
    for (int o = 16; o >= 1; o >>= 1) s += __shfl_xor_sync(0xffffffffu, s, o);
    if (lane == 0) red[w] = s;
    __syncthreads();
    float mu = (red[0] + red[1] + red[2] + red[3]) * (1.f / DIM);
    float d = v - mu;
    float q = d * d;
#pragma unroll
    for (int o = 16; o >= 1; o >>= 1) q += __shfl_xor_sync(0xffffffffu, q, o);
    __syncthreads();
    if (lane == 0) red[w] = q;
    __syncthreads();
    float var = (red[0] + red[1] + red[2] + red[3]) * (1.f / DIM);
    float r = d * rsqrtf(var + 1e-5f) * gamma[t] + beta[t];
    out[idx] = r;
    __half h = __float2half(r);
    ohi[idx] = h;
    olo[idx] = __float2half(r - __half2float(h));
}

__global__ void k_ln(const float* __restrict__ A, const float* __restrict__ Badd,
                     const float* __restrict__ gamma, const float* __restrict__ beta,
                     float* __restrict__ out)
{
    int g = blockIdx.x, t = threadIdx.x;
    size_t idx = (size_t)g * DIM + t;
    float v = A[idx] + Badd[idx];
    __shared__ float red[4];
    int lane = t & 31, w = t >> 5;
    float s = v;
#pragma unroll
    for (int o = 16; o >= 1; o >>= 1) s += __shfl_xor_sync(0xffffffffu, s, o);
    if (lane == 0) red[w] = s;
    __syncthreads();
    float mu = (red[0] + red[1] + red[2] + red[3]) * (1.f / DIM);
    float d = v - mu;
    float q = d * d;
#pragma unroll
    for (int o = 16; o >= 1; o >>= 1) q += __shfl_xor_sync(0xffffffffu, q, o);
    __syncthreads();
    if (lane == 0) red[w] = q;
    __syncthreads();
    float var = (red[0] + red[1] + red[2] + red[3]) * (1.f / DIM);
    out[idx] = d * rsqrtf(var + 1e-5f) * gamma[t] + beta[t];
}

// ---------------- launcher ----------------
extern "C" void kernel_launch(void* const* d_in, const int* in_sizes, int n_in,
                              void* d_out, int out_size)
{
    const float* x   = (const float*)d_in[0];
    const int*   ei  = (const int*)  d_in[1];
    const float* Wl  = (const float*)d_in[2];
    const float* bl  = (const float*)d_in[3];
    const float* Wr  = (const float*)d_in[4];
    const float* brv = (const float*)d_in[5];
    const float* att = (const float*)d_in[6];
    const float* bg  = (const float*)d_in[7];
    const float* W1  = (const float*)d_in[8];
    const float* b1  = (const float*)d_in[9];
    const float* W2  = (const float*)d_in[10];
    const float* b2  = (const float*)d_in[11];
    const float* g1  = (const float*)d_in[12];
    const float* be1 = (const float*)d_in[13];
    const float* g2  = (const float*)d_in[14];
    const float* be2 = (const float*)d_in[15];
    float* out = (float*)d_out;

    int E = in_sizes[1] / 2;
    if (E > EMAX) E = EMAX;

    cudaFuncSetAttribute(mmagemm, cudaFuncAttributeMaxDynamicSharedMemorySize, GSMEM);

    void *pagg, *ph, *phb, *pff1, *pxb, *pwlrt, *pw1t, *pw2t, *pblr;
    cudaGetSymbolAddress(&pagg,  g_agg);
    cudaGetSymbolAddress(&ph,    g_h);
    cudaGetSymbolAddress(&phb,   g_hb);
    cudaGetSymbolAddress(&pff1,  g_ff1);
    cudaGetSymbolAddress(&pxb,   g_xb);
    cudaGetSymbolAddress(&pwlrt, g_wlrt);
    cudaGetSymbolAddress(&pw1t,  g_w1t);
    cudaGetSymbolAddress(&pw2t,  g_w2t);
    cudaGetSymbolAddress(&pblr,  g_blr);

    __half* xbh = (__half*)pxb;
    __half* xbl = xbh + (size_t)TOT * DIM;
    __half* wlrt = (__half*)pwlrt;
    __half* w1t  = (__half*)pw1t;
    __half* w2t  = (__half*)pw2t;
    __half* hh   = (__half*)phb;
    __half* hl   = hh + (size_t)TOT * DIM;
    float*  xlr  = (float*)pff1;                       // [TOT,256], dead after k_edge
    __half* fh   = (__half*)pff1;                      // ff1 hi/lo (written after xlr dead)
    __half* fl   = fh + (size_t)TOT * FFD;

    // CSR build (base graph shared across instances)
    int gE = (E + 255) / 256;
    k_init   <<<1, 1024>>>();
    k_detect <<<gE, 256>>>(ei, E);
    k_decode <<<gE, 256>>>(ei, E);
    k_hist   <<<gE, 256>>>(E);
    k_scan   <<<1, 1024>>>();
    k_scatter<<<(E + NB + 255) / 256, 256>>>(E);

    // conversions: x hi/lo; weights single fp16 transposed; bias concat
    long n4 = (long)TOT * DIM / 4;
    k_cvt_x<<<(int)((n4 + 255) / 256), 256>>>(x, xbh, xbl, n4);
    k_cvt_w<<<(DIM * DIM + 255) / 256, 256>>>(Wl, wlrt,             DIM, DIM);
    k_cvt_w<<<(DIM * DIM + 255) / 256, 256>>>(Wr, wlrt + DIM * DIM, DIM, DIM);
    k_cvt_w<<<(DIM * FFD + 255) / 256, 256>>>(W1, w1t, DIM, FFD);
    k_cvt_w<<<(DIM * FFD + 255) / 256, 256>>>(W2, w2t, FFD, DIM);
    k_pack_bias<<<1, 256>>>(bl, brv);

    const int GM = (TOT + 127) / 128;   // 663

    // [x_l | x_r] = x @ [Wl|Wr] + [bl|br]  -> xlr [TOT,256] fp32
    mmagemm<<<dim3(GM, 2), 256, GSMEM>>>(xbh, xbl, wlrt, (const float*)pblr,
        xlr, nullptr, nullptr, TOT, 256, DIM, 0);

    // GATv2 aggregation
    k_edge<<<TOT, 128>>>(xlr, att, bg);

    // h = LN1(x + gat); emit fp32 + half hi/lo
    k_ln1<<<TOT, 128>>>(x, (const float*)pagg, g1, be1, (float*)ph, hh, hl);

    // ff1 = relu(h@W1 + b1) -> half hi/lo only
    mmagemm<<<dim3(GM, 16), 256, GSMEM>>>(hh, hl, w1t, b1,
        nullptr, fh, fl, TOT, FFD, DIM, 1);

    // ffn = ff1@W2 + b2 -> fp32 (g_agg)
    mmagemm<<<dim3(GM, 1), 256, GSMEM>>>(fh, fl, w2t, b2,
        (float*)pagg, nullptr, nullptr, TOT, DIM, FFD, 0);

    // out = LN2(h + ffn)
    k_ln<<<TOT, 128>>>((const float*)ph, (const float*)pagg, g2, be2, out);
}

// round 6
// speedup vs baseline: 3.4566x; 1.5213x over previous
#include <cuda_runtime.h>
#include <cuda_fp16.h>
#include <cstdint>

// ---------------- problem constants ----------------
#define NB    883
#define BTI   96
#define TOT   (NB*BTI)       // 84768
#define DIM   128
#define FFD   2048
#define EMAX  7168

// ---------------- device scratch ----------------
__device__ float g_agg[(size_t)TOT*DIM];
__device__ float g_h  [(size_t)TOT*DIM];
__device__ __half g_hb [(size_t)TOT*DIM];    // h fp16
__device__ float g_ff1[(size_t)TOT*FFD/2];   // xlr fp16 (TOT*256 halves) early; ff1 fp16 (TOT*2048 halves) later
__device__ __half g_xb [(size_t)TOT*DIM];    // x fp16
__device__ __half g_wlrt[256*DIM];           // [Wl;Wr] transposed: [256, 128]
__device__ __half g_w1t[(size_t)FFD*DIM];    // W1^T [2048,128]
__device__ __half g_w2t[(size_t)DIM*FFD];    // W2^T [128,2048]
__device__ float  g_blr[256];

__device__ int g_src[EMAX];
__device__ int g_dst[EMAX];
__device__ int g_deg[NB];
__device__ int g_rowptr[NB+1];
__device__ int g_wp[NB];
__device__ int g_csr[EMAX+NB];
__device__ int g_flag;

// ---------------- helpers ----------------
__device__ __forceinline__ uint32_t smem_u32(const void* p) {
    uint32_t a;
    asm("{ .reg .u64 t; cvta.to.shared.u64 t, %1; cvt.u32.u64 %0, t; }" : "=r"(a) : "l"(p));
    return a;
}
__device__ __forceinline__ void cp16(uint32_t s, const void* g) {
    asm volatile("cp.async.cg.shared.global [%0], [%1], 16;" :: "r"(s), "l"(g));
}
#define CP_COMMIT() asm volatile("cp.async.commit_group;" ::: "memory")
#define CP_WAIT1()  asm volatile("cp.async.wait_group 1;" ::: "memory")

__device__ __forceinline__ void ldm4(uint32_t* r, uint32_t addr) {
    asm volatile("ldmatrix.sync.aligned.m8n8.x4.shared.b16 {%0,%1,%2,%3}, [%4];"
        : "=r"(r[0]), "=r"(r[1]), "=r"(r[2]), "=r"(r[3]) : "r"(addr));
}
__device__ __forceinline__ void mma16816(float* d, const uint32_t* a, const uint32_t* b) {
    asm volatile(
        "mma.sync.aligned.m16n8k16.row.col.f32.f16.f16.f32 "
        "{%0,%1,%2,%3}, {%4,%5,%6,%7}, {%8,%9}, {%0,%1,%2,%3};"
        : "+f"(d[0]), "+f"(d[1]), "+f"(d[2]), "+f"(d[3])
        : "r"(a[0]), "r"(a[1]), "r"(a[2]), "r"(a[3]), "r"(b[0]), "r"(b[1]));
}

// ==================================================================================
// fp16 GEMM via mma.sync: C[M,N] = A[M,K] @ B[N,K]^T   (single-precision fp16 operands)
// BM=128, BN=128, BK=32, 3-stage cp.async, 256 threads, warp tile 32x64, 2 CTA/SM.
// smem per stage: A, B each 128 rows x 80B (64B data + 16B pad)
// ==================================================================================
#define SROWB   80
#define ARRB    (128*SROWB)          // 10240
#define STAGEB  (2*ARRB)             // 20480
#define GSMEM   (3*STAGEB)           // 61440

__global__ void __launch_bounds__(256, 2) mmagemm(
    const __half* __restrict__ A, const __half* __restrict__ B,
    const float* __restrict__ bias, float* __restrict__ C,
    __half* __restrict__ Oh,
    int M, int N, int K, int relu)
{
    extern __shared__ char smem[];
    const uint32_t sb = smem_u32(smem);
    const int tid = threadIdx.x;
    const int lane = tid & 31, wid = tid >> 5;
    const int wm = wid & 3, wn = wid >> 2;
    const int bm = blockIdx.x * 128, bn = blockIdx.y * 128;
    const int nk = K >> 5;

    auto load_stage = [&](int st, int kc) {
        int k0 = kc << 5;
        uint32_t base = sb + st * STAGEB;
#pragma unroll
        for (int j = 0; j < 4; j++) {
            int id = tid + 256 * j;
            int arr = id >> 9;            // 0=A 1=B
            int c = id & 511;
            int row = c >> 2, col = c & 3;
            const __half* src = (arr == 0) ? A : B;
            int gr = (arr == 0) ? min(bm + row, M - 1) : (bn + row);
            cp16(base + arr * ARRB + row * SROWB + col * 16,
                 src + (size_t)gr * K + k0 + col * 8);
        }
        CP_COMMIT();
    };

    float acc[2][8][4];
#pragma unroll
    for (int mi = 0; mi < 2; mi++)
#pragma unroll
        for (int ni = 0; ni < 8; ni++)
#pragma unroll
            for (int q = 0; q < 4; q++) acc[mi][ni][q] = 0.f;

    const uint32_t aoff = (uint32_t)((wm * 32 + (lane & 15)) * SROWB + ((lane >> 4) * 16));
    const uint32_t boff = (uint32_t)((wn * 64 + (lane & 7) + ((lane >> 4) << 3)) * SROWB
                                     + (((lane >> 3) & 1) * 16));

    load_stage(0, 0);
    load_stage(1, 1);

    for (int c = 0; c < nk; c++) {
        CP_WAIT1();
        __syncthreads();
        if (c + 2 < nk) load_stage((c + 2) % 3, c + 2);
        else CP_COMMIT();

        uint32_t s = sb + (c % 3) * STAGEB;
        uint32_t sA = s, sB = s + ARRB;
#pragma unroll
        for (int kk = 0; kk < 2; kk++) {
            uint32_t kb = kk * 32;
            uint32_t af[2][4], bf[4][4];
#pragma unroll
            for (int mi = 0; mi < 2; mi++)
                ldm4(af[mi], sA + aoff + mi * (16 * SROWB) + kb);
#pragma unroll
            for (int p = 0; p < 4; p++)
                ldm4(bf[p], sB + boff + p * (16 * SROWB) + kb);
#pragma unroll
            for (int mi = 0; mi < 2; mi++)
#pragma unroll
                for (int ni = 0; ni < 8; ni++)
                    mma16816(acc[mi][ni], af[mi], &bf[ni >> 1][(ni & 1) * 2]);
        }
        __syncthreads();
    }

    // epilogue
#pragma unroll
    for (int mi = 0; mi < 2; mi++) {
#pragma unroll
        for (int ni = 0; ni < 8; ni++) {
            int row0 = bm + wm * 32 + mi * 16 + (lane >> 2);
            int col  = bn + wn * 64 + ni * 8 + (lane & 3) * 2;
            float b0 = __ldg(bias + col), b1 = __ldg(bias + col + 1);
#pragma unroll
            for (int half_ = 0; half_ < 2; half_++) {
                int row = row0 + half_ * 8;
                if (row >= M) continue;
                float v0 = acc[mi][ni][half_ * 2 + 0] + b0;
                float v1 = acc[mi][ni][half_ * 2 + 1] + b1;
                if (relu) { v0 = fmaxf(v0, 0.f); v1 = fmaxf(v1, 0.f); }
                if (C)
                    *(float2*)(C + (size_t)row * N + col) = make_float2(v0, v1);
                if (Oh) {
                    __half2 hh; hh.x = __float2half(v0); hh.y = __float2half(v1);
                    *(__half2*)(Oh + (size_t)row * N + col) = hh;
                }
            }
        }
    }
}

// ---------------- conversion kernels ----------------
__global__ void k_cvt_x(const float* __restrict__ x, __half* __restrict__ o, long n4)
{
    long i = blockIdx.x * (long)blockDim.x + threadIdx.x;
    if (i >= n4) return;
    float4 v = ((const float4*)x)[i];
    long s = i * 4;
    __half2 a; a.x = __float2half(v.x); a.y = __float2half(v.y);
    __half2 b; b.x = __float2half(v.z); b.y = __float2half(v.w);
    *(__half2*)(o + s)     = a;
    *(__half2*)(o + s + 2) = b;
}

// transpose: W[K,N] -> out[N,K] fp16
__global__ void k_cvt_w(const float* __restrict__ W, __half* __restrict__ out, int K, int N)
{
    int i = blockIdx.x * blockDim.x + threadIdx.x;
    if (i >= K * N) return;
    int k = i / N, n = i - k * N;
    out[(size_t)n * K + k] = __float2half(W[i]);
}

__global__ void k_pack_bias(const float* __restrict__ bl, const float* __restrict__ br)
{
    int t = threadIdx.x;
    if (t < 128) g_blr[t] = bl[t];
    else         g_blr[t] = br[t - 128];
}

// ---------------- CSR build ----------------
__global__ void k_init() {
    int t = threadIdx.x;
    if (t < NB) g_deg[t] = 1;
    if (t == 0) g_flag = 0;
}
__global__ void k_detect(const int* __restrict__ w, int E) {
    int k = blockIdx.x * blockDim.x + threadIdx.x;
    if (k < E && w[2 * k + 1] != 0) atomicOr(&g_flag, 1);
}
__global__ void k_decode(const int* __restrict__ w, int E) {
    int k = blockIdx.x * blockDim.x + threadIdx.x;
    if (k >= E) return;
    if (g_flag == 0) { g_src[k] = w[2 * k]; g_dst[k] = w[2 * (E + k)]; }
    else             { g_src[k] = w[k];     g_dst[k] = w[E + k]; }
}
__global__ void k_hist(int E) {
    int k = blockIdx.x * blockDim.x + threadIdx.x;
    if (k < E) atomicAdd(&g_deg[g_dst[k]], 1);
}
__global__ void k_scan() {
    __shared__ int s[1024];
    int t = threadIdx.x;
    int v = (t < NB) ? g_deg[t] : 0;
    s[t] = v;
    __syncthreads();
    for (int off = 1; off < 1024; off <<= 1) {
        int u = (t >= off) ? s[t - off] : 0;
        __syncthreads();
        s[t] += u;
        __syncthreads();
    }
    if (t < NB) { g_rowptr[t + 1] = s[t]; g_wp[t] = s[t] - v; }
    if (t == 0) g_rowptr[0] = 0;
}
__global__ void k_scatter(int E) {
    int j = blockIdx.x * blockDim.x + threadIdx.x;
    if (j >= E + NB) return;
    int s, d;
    if (j < E) { s = g_src[j]; d = g_dst[j]; }
    else       { s = d = j - E; }
    g_csr[atomicAdd(&g_wp[d], 1)] = s;
}

// ---------------- GATv2 edge aggregation ----------------
// xlr: [TOT, 256] fp16, cols 0-127 = x_l, 128-255 = x_r.
// Scores are O(1) -> plain-exp softmax (no max subtraction; mathematically identical).
__global__ void k_edge(const __half* __restrict__ xlr,
                       const float* __restrict__ att, const float* __restrict__ bias_gat)
{
    int g = blockIdx.x;
    int b = g / NB;
    int i = g - b * NB;
    int t = threadIdx.x;
    float attv = att[t];
    float rx = __half2float(xlr[(size_t)g * 256 + 128 + t]);
    int e0 = g_rowptr[i], e1 = g_rowptr[i + 1];
    int base = b * NB;
    float ss = 0.f, acc = 0.f;
#pragma unroll 2
    for (int e = e0; e < e1; e++) {
        int sg = base + g_csr[e];
        float v  = __half2float(xlr[(size_t)sg * 256 + t]);
        float ev = v + rx;
        ev = ev > 0.f ? ev : 0.2f * ev;
        float p = ev * attv;
#pragma unroll
        for (int o = 8; o >= 1; o >>= 1)
            p += __shfl_xor_sync(0xffffffffu, p, o, 16);
        float w = __expf(p);
        ss  += w;
        acc += w * v;
    }
    g_agg[(size_t)g * DIM + t] = acc / ss + bias_gat[t];
}

// ---------------- LayerNorms ----------------
__global__ void k_ln1(const float* __restrict__ A, const float* __restrict__ Badd,
                      const float* __restrict__ gamma, const float* __restrict__ beta,
                      float* __restrict__ out, __half* __restrict__ oh)
{
    int g = blockIdx.x, t = threadIdx.x;
    size_t idx = (size_t)g * DIM + t;
    float v = A[idx] + Badd[idx];
    __shared__ float red[4];
    int lane = t & 31, w = t >> 5;
    float s = v;
#pragma unroll
    for (int o = 16; o >= 1; o >>= 1) s += __shfl_xor_sync(0xffffffffu, s, o);
    if (lane == 0) red[w] = s;
    __syncthreads();
    float mu = (red[0] + red[1] + red[2] + red[3]) * (1.f / DIM);
    float d = v - mu;
    float q = d * d;
#pragma unroll
    for (int o = 16; o >= 1; o >>= 1) q += __shfl_xor_sync(0xffffffffu, q, o);
    __syncthreads();
    if (lane == 0) red[w] = q;
    __syncthreads();
    float var = (red[0] + red[1] + red[2] + red[3]) * (1.f / DIM);
    float r = d * rsqrtf(var + 1e-5f) * gamma[t] + beta[t];
    out[idx] = r;
    oh[idx] = __float2half(r);
}

__global__ void k_ln(const float* __restrict__ A, const float* __restrict__ Badd,
                     const float* __restrict__ gamma, const float* __restrict__ beta,
                     float* __restrict__ out)
{
    int g = blockIdx.x, t = threadIdx.x;
    size_t idx = (size_t)g * DIM + t;
    float v = A[idx] + Badd[idx];
    __shared__ float red[4];
    int lane = t & 31, w = t >> 5;
    float s = v;
#pragma unroll
    for (int o = 16; o >= 1; o >>= 1) s += __shfl_xor_sync(0xffffffffu, s, o);
    if (lane == 0) red[w] = s;
    __syncthreads();
    float mu = (red[0] + red[1] + red[2] + red[3]) * (1.f / DIM);
    float d = v - mu;
    float q = d * d;
#pragma unroll
    for (int o = 16; o >= 1; o >>= 1) q += __shfl_xor_sync(0xffffffffu, q, o);
    __syncthreads();
    if (lane == 0) red[w] = q;
    __syncthreads();
    float var = (red[0] + red[1] + red[2] + red[3]) * (1.f / DIM);
    out[idx] = d * rsqrtf(var + 1e-5f) * gamma[t] + beta[t];
}

// ---------------- launcher ----------------
extern "C" void kernel_launch(void* const* d_in, const int* in_sizes, int n_in,
                              void* d_out, int out_size)
{
    const float* x   = (const float*)d_in[0];
    const int*   ei  = (const int*)  d_in[1];
    const float* Wl  = (const float*)d_in[2];
    const float* bl  = (const float*)d_in[3];
    const float* Wr  = (const float*)d_in[4];
    const float* brv = (const float*)d_in[5];
    const float* att = (const float*)d_in[6];
    const float* bg  = (const float*)d_in[7];
    const float* W1  = (const float*)d_in[8];
    const float* b1  = (const float*)d_in[9];
    const float* W2  = (const float*)d_in[10];
    const float* b2  = (const float*)d_in[11];
    const float* g1  = (const float*)d_in[12];
    const float* be1 = (const float*)d_in[13];
    const float* g2  = (const float*)d_in[14];
    const float* be2 = (const float*)d_in[15];
    float* out = (float*)d_out;

    int E = in_sizes[1] / 2;
    if (E > EMAX) E = EMAX;

    cudaFuncSetAttribute(mmagemm, cudaFuncAttributeMaxDynamicSharedMemorySize, GSMEM);

    void *pagg, *ph, *phb, *pff1, *pxb, *pwlrt, *pw1t, *pw2t, *pblr;
    cudaGetSymbolAddress(&pagg,  g_agg);
    cudaGetSymbolAddress(&ph,    g_h);
    cudaGetSymbolAddress(&phb,   g_hb);
    cudaGetSymbolAddress(&pff1,  g_ff1);
    cudaGetSymbolAddress(&pxb,   g_xb);
    cudaGetSymbolAddress(&pwlrt, g_wlrt);
    cudaGetSymbolAddress(&pw1t,  g_w1t);
    cudaGetSymbolAddress(&pw2t,  g_w2t);
    cudaGetSymbolAddress(&pblr,  g_blr);

    __half* xb   = (__half*)pxb;
    __half* wlrt = (__half*)pwlrt;
    __half* w1t  = (__half*)pw1t;
    __half* w2t  = (__half*)pw2t;
    __half* hh   = (__half*)phb;
    __half* xlr  = (__half*)pff1;       // [TOT,256] fp16, dead after k_edge
    __half* ff1  = (__half*)pff1;       // [TOT,2048] fp16, written after xlr dead

    // CSR build (base graph shared across instances)
    int gE = (E + 255) / 256;
    k_init   <<<1, 1024>>>();
    k_detect <<<gE, 256>>>(ei, E);
    k_decode <<<gE, 256>>>(ei, E);
    k_hist   <<<gE, 256>>>(E);
    k_scan   <<<1, 1024>>>();
    k_scatter<<<(E + NB + 255) / 256, 256>>>(E);

    // conversions
    long n4 = (long)TOT * DIM / 4;
    k_cvt_x<<<(int)((n4 + 255) / 256), 256>>>(x, xb, n4);
    k_cvt_w<<<(DIM * DIM + 255) / 256, 256>>>(Wl, wlrt,             DIM, DIM);
    k_cvt_w<<<(DIM * DIM + 255) / 256, 256>>>(Wr, wlrt + DIM * DIM, DIM, DIM);
    k_cvt_w<<<(DIM * FFD + 255) / 256, 256>>>(W1, w1t, DIM, FFD);
    k_cvt_w<<<(DIM * FFD + 255) / 256, 256>>>(W2, w2t, FFD, DIM);
    k_pack_bias<<<1, 256>>>(bl, brv);

    const int GM = (TOT + 127) / 128;   // 663

    // [x_l | x_r] = x @ [Wl|Wr] + [bl|br]  -> xlr [TOT,256] fp16
    mmagemm<<<dim3(GM, 2), 256, GSMEM>>>(xb, wlrt, (const float*)pblr,
        nullptr, xlr, TOT, 256, DIM, 0);

    // GATv2 aggregation
    k_edge<<<TOT, 128>>>(xlr, att, bg);

    // h = LN1(x + gat); emit fp32 + fp16
    k_ln1<<<TOT, 128>>>(x, (const float*)pagg, g1, be1, (float*)ph, hh);

    // ff1 = relu(h@W1 + b1) -> fp16
    mmagemm<<<dim3(GM, 16), 256, GSMEM>>>(hh, w1t, b1,
        nullptr, ff1, TOT, FFD, DIM, 1);

    // ffn = ff1@W2 + b2 -> fp32 (g_agg)
    mmagemm<<<dim3(GM, 1), 256, GSMEM>>>(ff1, w2t, b2,
        (float*)pagg, nullptr, TOT, DIM, FFD, 0);

    // out = LN2(h + ffn)
    k_ln<<<TOT, 128>>>((const float*)ph, (const float*)pagg, g2, be2, out);
}

// round 7
// speedup vs baseline: 3.8348x; 1.1094x over previous
#include <cuda_runtime.h>
#include <cuda_fp16.h>
#include <cstdint>

// ---------------- problem constants ----------------
#define NB    883
#define BTI   96
#define TOT   (NB*BTI)       // 84768
#define DIM   128
#define FFD   2048
#define EMAX  7168

// ---------------- device scratch ----------------
__device__ float g_agg [(size_t)TOT*DIM];
__device__ float g_agg2[(size_t)TOT*DIM];
__device__ float g_h  [(size_t)TOT*DIM];
__device__ __half g_hb [(size_t)TOT*DIM];    // h fp16
__device__ float g_ff1[(size_t)TOT*FFD/2];   // xlr fp16 (TOT*256) early; ff1 fp16 (TOT*2048) later
__device__ __half g_xb [(size_t)TOT*DIM];    // x fp16
__device__ __half g_wlrt[256*DIM];           // [Wl;Wr] transposed: [256, 128]
__device__ __half g_w1t[(size_t)FFD*DIM];    // W1^T [2048,128]
__device__ __half g_w2t[(size_t)DIM*FFD];    // W2^T [128,2048]
__device__ float  g_blr[256];

__device__ int g_src[EMAX];
__device__ int g_dst[EMAX];
__device__ int g_deg[NB];
__device__ int g_rowptr[NB+1];
__device__ int g_wp[NB];
__device__ int g_csr[EMAX+NB];
__device__ int g_flag;   // sticky across replays: OR-idempotent => deterministic output

// ---------------- helpers ----------------
__device__ __forceinline__ uint32_t smem_u32(const void* p) {
    uint32_t a;
    asm("{ .reg .u64 t; cvta.to.shared.u64 t, %1; cvt.u32.u64 %0, t; }" : "=r"(a) : "l"(p));
    return a;
}
__device__ __forceinline__ void cp16(uint32_t s, const void* g) {
    asm volatile("cp.async.cg.shared.global [%0], [%1], 16;" :: "r"(s), "l"(g));
}
#define CP_COMMIT() asm volatile("cp.async.commit_group;" ::: "memory")
#define CP_WAIT1()  asm volatile("cp.async.wait_group 1;" ::: "memory")

__device__ __forceinline__ void ldm4(uint32_t* r, uint32_t addr) {
    asm volatile("ldmatrix.sync.aligned.m8n8.x4.shared.b16 {%0,%1,%2,%3}, [%4];"
        : "=r"(r[0]), "=r"(r[1]), "=r"(r[2]), "=r"(r[3]) : "r"(addr));
}
__device__ __forceinline__ void mma16816(float* d, const uint32_t* a, const uint32_t* b) {
    asm volatile(
        "mma.sync.aligned.m16n8k16.row.col.f32.f16.f16.f32 "
        "{%0,%1,%2,%3}, {%4,%5,%6,%7}, {%8,%9}, {%0,%1,%2,%3};"
        : "+f"(d[0]), "+f"(d[1]), "+f"(d[2]), "+f"(d[3])
        : "r"(a[0]), "r"(a[1]), "r"(a[2]), "r"(a[3]), "r"(b[0]), "r"(b[1]));
}

// ==================================================================================
// fp16 GEMM via mma.sync: C[M,N] = A[M,K] @ B[N,K]^T
// BM=128, BN=128, BK=32, 3-stage cp.async, 256 threads, warp tile 32x64, 2 CTA/SM.
// ==================================================================================
#define SROWB   80
#define ARRB    (128*SROWB)
#define STAGEB  (2*ARRB)
#define GSMEM   (3*STAGEB)           // 61440

__global__ void __launch_bounds__(256, 2) mmagemm(
    const __half* __restrict__ A, const __half* __restrict__ B,
    const float* __restrict__ bias, float* __restrict__ C,
    __half* __restrict__ Oh,
    int M, int N, int K, int lda, int ldb, int relu)
{
    extern __shared__ char smem[];
    const uint32_t sb = smem_u32(smem);
    const int tid = threadIdx.x;
    const int lane = tid & 31, wid = tid >> 5;
    const int wm = wid & 3, wn = wid >> 2;
    const int bm = blockIdx.x * 128, bn = blockIdx.y * 128;
    const int nk = K >> 5;

    auto load_stage = [&](int st, int kc) {
        int k0 = kc << 5;
        uint32_t base = sb + st * STAGEB;
#pragma unroll
        for (int j = 0; j < 4; j++) {
            int id = tid + 256 * j;
            int arr = id >> 9;            // 0=A 1=B
            int c = id & 511;
            int row = c >> 2, col = c & 3;
            const __half* g;
            if (arr == 0) g = A + (size_t)min(bm + row, M - 1) * lda + k0 + col * 8;
            else          g = B + (size_t)(bn + row) * ldb + k0 + col * 8;
            cp16(base + arr * ARRB + row * SROWB + col * 16, g);
        }
        CP_COMMIT();
    };

    float acc[2][8][4];
#pragma unroll
    for (int mi = 0; mi < 2; mi++)
#pragma unroll
        for (int ni = 0; ni < 8; ni++)
#pragma unroll
            for (int q = 0; q < 4; q++) acc[mi][ni][q] = 0.f;

    const uint32_t aoff = (uint32_t)((wm * 32 + (lane & 15)) * SROWB + ((lane >> 4) * 16));
    const uint32_t boff = (uint32_t)((wn * 64 + (lane & 7) + ((lane >> 4) << 3)) * SROWB
                                     + (((lane >> 3) & 1) * 16));

    load_stage(0, 0);
    load_stage(1, 1);

    for (int c = 0; c < nk; c++) {
        CP_WAIT1();
        __syncthreads();
        if (c + 2 < nk) load_stage((c + 2) % 3, c + 2);
        else CP_COMMIT();

        uint32_t s = sb + (c % 3) * STAGEB;
        uint32_t sA = s, sB = s + ARRB;
#pragma unroll
        for (int kk = 0; kk < 2; kk++) {
            uint32_t kb = kk * 32;
            uint32_t af[2][4], bf[4][4];
#pragma unroll
            for (int mi = 0; mi < 2; mi++)
                ldm4(af[mi], sA + aoff + mi * (16 * SROWB) + kb);
#pragma unroll
            for (int p = 0; p < 4; p++)
                ldm4(bf[p], sB + boff + p * (16 * SROWB) + kb);
#pragma unroll
            for (int mi = 0; mi < 2; mi++)
#pragma unroll
                for (int ni = 0; ni < 8; ni++)
                    mma16816(acc[mi][ni], af[mi], &bf[ni >> 1][(ni & 1) * 2]);
        }
        __syncthreads();
    }

    // epilogue
#pragma unroll
    for (int mi = 0; mi < 2; mi++) {
#pragma unroll
        for (int ni = 0; ni < 8; ni++) {
            int row0 = bm + wm * 32 + mi * 16 + (lane >> 2);
            int col  = bn + wn * 64 + ni * 8 + (lane & 3) * 2;
            float b0 = bias ? __ldg(bias + col)     : 0.f;
            float b1 = bias ? __ldg(bias + col + 1) : 0.f;
#pragma unroll
            for (int half_ = 0; half_ < 2; half_++) {
                int row = row0 + half_ * 8;
                if (row >= M) continue;
                float v0 = acc[mi][ni][half_ * 2 + 0] + b0;
                float v1 = acc[mi][ni][half_ * 2 + 1] + b1;
                if (relu) { v0 = fmaxf(v0, 0.f); v1 = fmaxf(v1, 0.f); }
                if (C)
                    *(float2*)(C + (size_t)row * N + col) = make_float2(v0, v1);
                if (Oh) {
                    __half2 hh; hh.x = __float2half(v0); hh.y = __float2half(v1);
                    *(__half2*)(Oh + (size_t)row * N + col) = hh;
                }
            }
        }
    }
}

// ---------------- merged prelude kernels ----------------
// launch 1: reset degrees + detect int64-vs-int32 layout
__global__ void k_init_detect(const int* __restrict__ w, int E) {
    int k = blockIdx.x * blockDim.x + threadIdx.x;
    if (k < NB) g_deg[k] = 1;                     // self loop
    if (k < E && w[2 * k + 1] != 0) atomicOr(&g_flag, 1);
}
// launch 2: decode edges + histogram dst degrees
__global__ void k_decode_hist(const int* __restrict__ w, int E) {
    int k = blockIdx.x * blockDim.x + threadIdx.x;
    if (k >= E) return;
    int s, d;
    if (g_flag == 0) { s = w[2 * k]; d = w[2 * (E + k)]; }
    else             { s = w[k];     d = w[E + k]; }
    g_src[k] = s;
    g_dst[k] = d;
    atomicAdd(&g_deg[d], 1);
}
// launch 3: all fp16 conversions + weight transposes + bias pack in one kernel
__global__ void k_cvt_all(const float* __restrict__ x,
                          const float* __restrict__ Wl, const float* __restrict__ Wr,
                          const float* __restrict__ W1, const float* __restrict__ W2,
                          const float* __restrict__ bl, const float* __restrict__ br)
{
    const long N0 = (long)TOT * DIM / 4;
    long id = (long)blockIdx.x * blockDim.x + threadIdx.x;
    if (id < N0) {
        float4 v = ((const float4*)x)[id];
        long s = id * 4;
        __half2 a; a.x = __float2half(v.x); a.y = __float2half(v.y);
        __half2 b; b.x = __float2half(v.z); b.y = __float2half(v.w);
        *(__half2*)(g_xb + s)     = a;
        *(__half2*)(g_xb + s + 2) = b;
        return;
    }
    id -= N0;
    if (id < DIM * DIM) {            // Wl [128,128] -> wlrt rows 0..127
        int k = (int)id / DIM, n = (int)id % DIM;
        g_wlrt[(size_t)n * DIM + k] = __float2half(Wl[id]);
        return;
    }
    id -= DIM * DIM;
    if (id < DIM * DIM) {            // Wr -> wlrt rows 128..255
        int k = (int)id / DIM, n = (int)id % DIM;
        g_wlrt[(size_t)(128 + n) * DIM + k] = __float2half(Wr[id]);
        return;
    }
    id -= DIM * DIM;
    if (id < (long)DIM * FFD) {      // W1 [128,2048] -> w1t [2048,128]
        int k = (int)(id / FFD), n = (int)(id % FFD);
        g_w1t[(size_t)n * DIM + k] = __float2half(W1[id]);
        return;
    }
    id -= (long)DIM * FFD;
    if (id < (long)DIM * FFD) {      // W2 [2048,128] -> w2t [128,2048]
        int k = (int)(id / DIM), n = (int)(id % DIM);
        g_w2t[(size_t)n * FFD + k] = __float2half(W2[id]);
        return;
    }
    id -= (long)DIM * FFD;
    if (id < 256) {
        g_blr[id] = (id < 128) ? bl[id] : br[id - 128];
    }
}

__global__ void k_scan() {
    __shared__ int s[1024];
    int t = threadIdx.x;
    int v = (t < NB) ? g_deg[t] : 0;
    s[t] = v;
    __syncthreads();
    for (int off = 1; off < 1024; off <<= 1) {
        int u = (t >= off) ? s[t - off] : 0;
        __syncthreads();
        s[t] += u;
        __syncthreads();
    }
    if (t < NB) { g_rowptr[t + 1] = s[t]; g_wp[t] = s[t] - v; }
    if (t == 0) g_rowptr[0] = 0;
}
__global__ void k_scatter(int E) {
    int j = blockIdx.x * blockDim.x + threadIdx.x;
    if (j >= E + NB) return;
    int s, d;
    if (j < E) { s = g_src[j]; d = g_dst[j]; }
    else       { s = d = j - E; }
    g_csr[atomicAdd(&g_wp[d], 1)] = s;
}

// ---------------- fused GATv2 edge aggregation + LN1 ----------------
// Block: 256 threads = 4 groups x 64; group = one node-instance (same base node i,
// 4 consecutive b's => identical edge trip counts, shared CSR lines in L1).
// Thread t2 in group handles channels {2*t2, 2*t2+1} (half2).
// Plain-exp softmax (scores are O(1): mathematically identical, no overflow risk).
__global__ void __launch_bounds__(256) k_edge_ln1(
    const __half* __restrict__ xlr, const float* __restrict__ x,
    const float* __restrict__ att, const float* __restrict__ bias_gat,
    const float* __restrict__ gamma, const float* __restrict__ beta,
    float* __restrict__ hout, __half* __restrict__ hhout)
{
    __shared__ float redS[4][2], redQ[4][2];
    const int i = blockIdx.x;
    const int gidx = threadIdx.x >> 6;
    const int t2 = threadIdx.x & 63;
    const int b = blockIdx.y * 4 + gidx;
    const int g = b * NB + i;
    const int base = b * NB;

    float2 attv = *(const float2*)(att + 2 * t2);
    __half2 rx2 = *(const __half2*)(xlr + (size_t)g * 256 + 128 + 2 * t2);
    float rx0 = __half2float(rx2.x), rx1 = __half2float(rx2.y);

    const int e0 = g_rowptr[i], e1 = g_rowptr[i + 1];
    float ss = 0.f, a0 = 0.f, a1 = 0.f;
#pragma unroll 2
    for (int e = e0; e < e1; e++) {
        int sg = base + g_csr[e];
        __half2 v2 = *(const __half2*)(xlr + (size_t)sg * 256 + 2 * t2);
        float v0 = __half2float(v2.x), v1 = __half2float(v2.y);
        float e0f = v0 + rx0, e1f = v1 + rx1;
        e0f = e0f > 0.f ? e0f : 0.2f * e0f;
        e1f = e1f > 0.f ? e1f : 0.2f * e1f;
        float p = e0f * attv.x + e1f * attv.y;
        p += __shfl_xor_sync(0xffffffffu, p, 4, 8);
        p += __shfl_xor_sync(0xffffffffu, p, 2, 8);
        p += __shfl_xor_sync(0xffffffffu, p, 1, 8);
        float w = __expf(p);
        ss += w;
        a0 += w * v0;
        a1 += w * v1;
    }
    float2 bg2 = *(const float2*)(bias_gat + 2 * t2);
    float inv = 1.f / ss;
    float r0 = a0 * inv + bg2.x;
    float r1 = a1 * inv + bg2.y;

    // LN1 over this instance's 128 channels (held by 64 threads x2)
    float2 xv = *(const float2*)(x + (size_t)g * DIM + 2 * t2);
    float v0 = xv.x + r0, v1 = xv.y + r1;

    int wg = t2 >> 5, lane = t2 & 31;
    float s = v0 + v1;
#pragma unroll
    for (int o = 16; o >= 1; o >>= 1) s += __shfl_xor_sync(0xffffffffu, s, o);
    if (lane == 0) redS[gidx][wg] = s;
    __syncthreads();
    float mu = (redS[gidx][0] + redS[gidx][1]) * (1.f / DIM);
    float d0 = v0 - mu, d1 = v1 - mu;
    float q = d0 * d0 + d1 * d1;
#pragma unroll
    for (int o = 16; o >= 1; o >>= 1) q += __shfl_xor_sync(0xffffffffu, q, o);
    if (lane == 0) redQ[gidx][wg] = q;
    __syncthreads();
    float var = (redQ[gidx][0] + redQ[gidx][1]) * (1.f / DIM);
    float rstd = rsqrtf(var + 1e-5f);
    float2 gm = *(const float2*)(gamma + 2 * t2);
    float2 be = *(const float2*)(beta  + 2 * t2);
    float h0 = d0 * rstd * gm.x + be.x;
    float h1 = d1 * rstd * gm.y + be.y;
    *(float2*)(hout + (size_t)g * DIM + 2 * t2) = make_float2(h0, h1);
    __half2 hh; hh.x = __float2half(h0); hh.y = __float2half(h1);
    *(__half2*)(hhout + (size_t)g * DIM + 2 * t2) = hh;
}

// ---------------- LN2: out = LN(h + agg + agg2) ----------------
__global__ void k_ln3(const float* __restrict__ A, const float* __restrict__ B1,
                      const float* __restrict__ B2,
                      const float* __restrict__ gamma, const float* __restrict__ beta,
                      float* __restrict__ out)
{
    int g = blockIdx.x, t = threadIdx.x;
    size_t idx = (size_t)g * DIM + t;
    float v = A[idx] + B1[idx] + B2[idx];
    __shared__ float red[4];
    int lane = t & 31, w = t >> 5;
    float s = v;
#pragma unroll
    for (int o = 16; o >= 1; o >>= 1) s += __shfl_xor_sync(0xffffffffu, s, o);
    if (lane == 0) red[w] = s;
    __syncthreads();
    float mu = (red[0] + red[1] + red[2] + red[3]) * (1.f / DIM);
    float d = v - mu;
    float q = d * d;
#pragma unroll
    for (int o = 16; o >= 1; o >>= 1) q += __shfl_xor_sync(0xffffffffu, q, o);
    __syncthreads();
    if (lane == 0) red[w] = q;
    __syncthreads();
    float var = (red[0] + red[1] + red[2] + red[3]) * (1.f / DIM);
    out[idx] = d * rsqrtf(var + 1e-5f) * gamma[t] + beta[t];
}

// ---------------- launcher ----------------
extern "C" void kernel_launch(void* const* d_in, const int* in_sizes, int n_in,
                              void* d_out, int out_size)
{
    const float* x   = (const float*)d_in[0];
    const int*   ei  = (const int*)  d_in[1];
    const float* Wl  = (const float*)d_in[2];
    const float* bl  = (const float*)d_in[3];
    const float* Wr  = (const float*)d_in[4];
    const float* brv = (const float*)d_in[5];
    const float* att = (const float*)d_in[6];
    const float* bg  = (const float*)d_in[7];
    const float* W1  = (const float*)d_in[8];
    const float* b1  = (const float*)d_in[9];
    const float* W2  = (const float*)d_in[10];
    const float* b2  = (const float*)d_in[11];
    const float* g1  = (const float*)d_in[12];
    const float* be1 = (const float*)d_in[13];
    const float* g2  = (const float*)d_in[14];
    const float* be2 = (const float*)d_in[15];
    float* out = (float*)d_out;

    int E = in_sizes[1] / 2;
    if (E > EMAX) E = EMAX;

    cudaFuncSetAttribute(mmagemm, cudaFuncAttributeMaxDynamicSharedMemorySize, GSMEM);

    void *pagg, *pagg2, *ph, *phb, *pff1, *pxb, *pwlrt, *pw1t, *pw2t, *pblr;
    cudaGetSymbolAddress(&pagg,  g_agg);
    cudaGetSymbolAddress(&pagg2, g_agg2);
    cudaGetSymbolAddress(&ph,    g_h);
    cudaGetSymbolAddress(&phb,   g_hb);
    cudaGetSymbolAddress(&pff1,  g_ff1);
    cudaGetSymbolAddress(&pxb,   g_xb);
    cudaGetSymbolAddress(&pwlrt, g_wlrt);
    cudaGetSymbolAddress(&pw1t,  g_w1t);
    cudaGetSymbolAddress(&pw2t,  g_w2t);
    cudaGetSymbolAddress(&pblr,  g_blr);

    __half* xb   = (__half*)pxb;
    __half* wlrt = (__half*)pwlrt;
    __half* w1t  = (__half*)pw1t;
    __half* w2t  = (__half*)pw2t;
    __half* hh   = (__half*)phb;
    __half* xlr  = (__half*)pff1;       // [TOT,256] fp16, dead after k_edge_ln1
    __half* ff1  = (__half*)pff1;       // [TOT,2048] fp16, written after xlr dead

    const int GM = (TOT + 127) / 128;   // 663
    const long NCVT = (long)TOT * DIM / 4 + 2L * DIM * DIM + 2L * DIM * FFD + 256;
    const int GCVT = (int)((NCVT + 255) / 256);
    int gE = (E + 255) / 256;

    // 1-2: edge decode + degree histogram
    k_init_detect<<<gE, 256>>>(ei, E);
    k_decode_hist<<<gE, 256>>>(ei, E);
    // 3: all conversions
    k_cvt_all<<<GCVT, 256>>>(x, Wl, Wr, W1, W2, bl, brv);
    // 4: [x_l | x_r] = x @ [Wl|Wr] + [bl|br]  (this is the ncu-captured launch)
    mmagemm<<<dim3(GM, 2), 256, GSMEM>>>(xb, wlrt, (const float*)pblr,
        nullptr, xlr, TOT, 256, DIM, DIM, DIM, 0);
    // 5-6: CSR finalize
    k_scan<<<1, 1024>>>();
    k_scatter<<<(E + NB + 255) / 256, 256>>>(E);
    // 7: GATv2 aggregation + LN1 fused -> h (fp32 + fp16)
    k_edge_ln1<<<dim3(NB, BTI / 4), 256>>>(xlr, x, att, bg, g1, be1, (float*)ph, hh);
    // 8: ff1 = relu(h@W1 + b1) -> fp16
    mmagemm<<<dim3(GM, 16), 256, GSMEM>>>(hh, w1t, b1,
        nullptr, ff1, TOT, FFD, DIM, DIM, DIM, 1);
    // 9-10: ffn = ff1@W2 + b2, split-K (deterministic two-buffer accumulation)
    mmagemm<<<dim3(GM, 1), 256, GSMEM>>>(ff1, w2t, b2,
        (float*)pagg, nullptr, TOT, DIM, 1024, FFD, FFD, 0);
    mmagemm<<<dim3(GM, 1), 256, GSMEM>>>(ff1 + 1024, w2t + 1024, nullptr,
        (float*)pagg2, nullptr, TOT, DIM, 1024, FFD, FFD, 0);
    // 11: out = LN2(h + ffn)
    k_ln3<<<TOT, 128>>>((const float*)ph, (const float*)pagg, (const float*)pagg2,
                        g2, be2, out);
}